// round 5
// baseline (speedup 1.0000x reference)
#include <cuda_runtime.h>

#define NN 50000
#define EE 500000
#define HH 128
#define GG 256

// ---------------- scratch (device globals; no allocs allowed) ----------------
static __device__ __align__(16) float g_buf0[(size_t)NN * HH];   // GEMM outputs
static __device__ __align__(16) float g_buf1[(size_t)NN * HH];   // aggregated/relu outputs
static __device__ float g_deg[NN];
static __device__ float g_dinv[NN];
static __device__ int   g_cnt[NN];     // in-degree (edge count, no self loop)
static __device__ int   g_off[NN];     // CSR row offsets (exclusive scan of g_cnt)
static __device__ int   g_pos[EE];     // per-edge slot within its dst bucket
static __device__ int   g_csrc[EE];    // CSR: source node per edge
static __device__ float g_cw[EE];      // CSR: edge weight
static __device__ __align__(16) float g_pooled[GG * HH];
static __device__ float g_gcnt[GG];

// ---------------- setup kernels ----------------
__global__ void init_kernel() {
    int i = blockIdx.x * blockDim.x + threadIdx.x;
    if (i < NN) { g_deg[i] = 1.0f; g_cnt[i] = 0; }   // deg starts at 1 (self loop w=1)
    if (i < GG * HH) g_pooled[i] = 0.0f;
    if (i < GG) g_gcnt[i] = 0.0f;
}

__global__ void count_kernel(const int* __restrict__ dst, const float* __restrict__ ew) {
    int e = blockIdx.x * blockDim.x + threadIdx.x;
    if (e >= EE) return;
    int d = dst[e];
    atomicAdd(&g_deg[d], ew[e]);
    g_pos[e] = atomicAdd(&g_cnt[d], 1);
}

// single-block exclusive scan of g_cnt -> g_off (N=50000, 49 chunk iterations)
__global__ void scan_kernel() {
    __shared__ int sh[1024];
    __shared__ int s_carry;
    int tid = threadIdx.x;
    if (tid == 0) s_carry = 0;
    __syncthreads();
    for (int base = 0; base < NN; base += 1024) {
        int i = base + tid;
        int v = (i < NN) ? g_cnt[i] : 0;
        sh[tid] = v;
        __syncthreads();
        #pragma unroll
        for (int s = 1; s < 1024; s <<= 1) {
            int t = (tid >= s) ? sh[tid - s] : 0;
            __syncthreads();
            sh[tid] += t;
            __syncthreads();
        }
        int c0 = s_carry;
        if (i < NN) g_off[i] = c0 + sh[tid] - v;
        __syncthreads();                     // all reads of s_carry/sh done
        if (tid == 0) s_carry = c0 + sh[1023];
        __syncthreads();
    }
}

__global__ void scatter_kernel(const int* __restrict__ src, const int* __restrict__ dst,
                               const float* __restrict__ ew) {
    int e = blockIdx.x * blockDim.x + threadIdx.x;
    if (e >= EE) return;
    int d = dst[e];
    int idx = g_off[d] + g_pos[e];
    g_csrc[idx] = src[e];
    g_cw[idx]   = ew[e];
}

__global__ void dinv_kernel() {
    int i = blockIdx.x * blockDim.x + threadIdx.x;
    if (i < NN) g_dinv[i] = rsqrtf(g_deg[i]);   // deg >= 1 always
}

// ---------------- SGEMM: C[NN x 128] = A[NN x 128] * W^T, W is [128 x 128] ----
#define BM 64
#define BN 64
#define BK 16
#define PAD 68   // 68*4 = 272 B: 16B-aligned row stride, breaks store conflicts

__global__ void gemm_kernel(const float* __restrict__ A, const float* __restrict__ W,
                            float* __restrict__ C) {
    __shared__ __align__(16) float As[BK][PAD];
    __shared__ __align__(16) float Bs[BK][PAD];
    int t = threadIdx.x;                 // 256 threads
    int tx = t & 15, ty = t >> 4;
    int rowBase = blockIdx.x * BM;
    int colBase = blockIdx.y * BN;
    int lr = t >> 2;                     // 0..63 loader row
    int lk = (t & 3) << 2;               // 0,4,8,12 loader k
    float acc[4][4] = {};

    for (int k0 = 0; k0 < HH; k0 += BK) {
        float4 av = make_float4(0.f, 0.f, 0.f, 0.f);
        int arow = rowBase + lr;
        if (arow < NN)
            av = *reinterpret_cast<const float4*>(A + (size_t)arow * HH + k0 + lk);
        As[lk + 0][lr] = av.x; As[lk + 1][lr] = av.y;
        As[lk + 2][lr] = av.z; As[lk + 3][lr] = av.w;

        float4 wv = *reinterpret_cast<const float4*>(W + (size_t)(colBase + lr) * HH + k0 + lk);
        Bs[lk + 0][lr] = wv.x; Bs[lk + 1][lr] = wv.y;
        Bs[lk + 2][lr] = wv.z; Bs[lk + 3][lr] = wv.w;
        __syncthreads();

        #pragma unroll
        for (int k = 0; k < BK; k++) {
            float4 a = *reinterpret_cast<const float4*>(&As[k][ty << 2]);
            float4 b = *reinterpret_cast<const float4*>(&Bs[k][tx << 2]);
            acc[0][0] += a.x * b.x; acc[0][1] += a.x * b.y; acc[0][2] += a.x * b.z; acc[0][3] += a.x * b.w;
            acc[1][0] += a.y * b.x; acc[1][1] += a.y * b.y; acc[1][2] += a.y * b.z; acc[1][3] += a.y * b.w;
            acc[2][0] += a.z * b.x; acc[2][1] += a.z * b.y; acc[2][2] += a.z * b.z; acc[2][3] += a.z * b.w;
            acc[3][0] += a.w * b.x; acc[3][1] += a.w * b.y; acc[3][2] += a.w * b.z; acc[3][3] += a.w * b.w;
        }
        __syncthreads();
    }

    #pragma unroll
    for (int i = 0; i < 4; i++) {
        int r = rowBase + (ty << 2) + i;
        if (r < NN) {
            float4 v = make_float4(acc[i][0], acc[i][1], acc[i][2], acc[i][3]);
            *reinterpret_cast<float4*>(C + (size_t)r * HH + colBase + (tx << 2)) = v;
        }
    }
}

// ---------------- aggregation: out[n] = relu(sum_in h[s]*norm + h[n]*dinv^2 + b) --
__global__ void agg_kernel(const float* __restrict__ h, const float* __restrict__ bias,
                           float* __restrict__ out) {
    int w = (blockIdx.x * blockDim.x + threadIdx.x) >> 5;
    int lane = threadIdx.x & 31;
    if (w >= NN) return;
    int n = w;
    float dn = g_dinv[n];
    float4 hv = *reinterpret_cast<const float4*>(h + (size_t)n * HH + (lane << 2));
    float sn = dn * dn;                       // self loop: dinv[n]*1*dinv[n]
    float4 acc = make_float4(hv.x * sn, hv.y * sn, hv.z * sn, hv.w * sn);
    int o = g_off[n], c = g_cnt[n];
    for (int j = 0; j < c; j++) {
        int s = g_csrc[o + j];
        float nr = g_dinv[s] * g_cw[o + j] * dn;
        float4 v = *reinterpret_cast<const float4*>(h + (size_t)s * HH + (lane << 2));
        acc.x += v.x * nr; acc.y += v.y * nr; acc.z += v.z * nr; acc.w += v.w * nr;
    }
    float4 b = *reinterpret_cast<const float4*>(bias + (lane << 2));
    float4 r = make_float4(fmaxf(acc.x + b.x, 0.f), fmaxf(acc.y + b.y, 0.f),
                           fmaxf(acc.z + b.z, 0.f), fmaxf(acc.w + b.w, 0.f));
    *reinterpret_cast<float4*>(out + (size_t)n * HH + (lane << 2)) = r;
}

// ---------------- pooling: batch is sorted, accumulate runs, flush w/ atomics ----
#define CHUNK 32
__global__ void pool_kernel(const float* __restrict__ h, const int* __restrict__ batch) {
    int w = (blockIdx.x * blockDim.x + threadIdx.x) >> 5;
    int lane = threadIdx.x & 31;
    int start = w * CHUNK;
    if (start >= NN) return;
    int end = min(NN, start + CHUNK);
    int cur = batch[start];
    float4 acc = make_float4(0.f, 0.f, 0.f, 0.f);
    float cnt = 0.f;
    for (int i = start; i < end; i++) {
        int g = batch[i];
        if (g != cur) {
            float* p = &g_pooled[(size_t)cur * HH + (lane << 2)];
            atomicAdd(p + 0, acc.x); atomicAdd(p + 1, acc.y);
            atomicAdd(p + 2, acc.z); atomicAdd(p + 3, acc.w);
            if (lane == 0) atomicAdd(&g_gcnt[cur], cnt);
            acc = make_float4(0.f, 0.f, 0.f, 0.f); cnt = 0.f; cur = g;
        }
        float4 v = *reinterpret_cast<const float4*>(h + (size_t)i * HH + (lane << 2));
        acc.x += v.x; acc.y += v.y; acc.z += v.z; acc.w += v.w;
        cnt += 1.f;
    }
    float* p = &g_pooled[(size_t)cur * HH + (lane << 2)];
    atomicAdd(p + 0, acc.x); atomicAdd(p + 1, acc.y);
    atomicAdd(p + 2, acc.z); atomicAdd(p + 3, acc.w);
    if (lane == 0) atomicAdd(&g_gcnt[cur], cnt);
}

// ---------------- head MLP: out[g] = fW2 @ relu(fW1 @ mean + fb1) + fb2 ----------
__global__ void mlp_kernel(const float* __restrict__ fW1, const float* __restrict__ fb1,
                           const float* __restrict__ fW2, const float* __restrict__ fb2,
                           float* __restrict__ out) {
    __shared__ float p[HH];
    __shared__ float red[4];
    int g = blockIdx.x, j = threadIdx.x;   // 128 threads
    float c = fmaxf(g_gcnt[g], 1.0f);
    p[j] = g_pooled[(size_t)g * HH + j] / c;
    __syncthreads();
    float acc = fb1[j];
    #pragma unroll 8
    for (int k = 0; k < HH; k++) acc += p[k] * fW1[(size_t)j * HH + k];
    float o = fmaxf(acc, 0.f) * fW2[j];
    #pragma unroll
    for (int s = 16; s > 0; s >>= 1) o += __shfl_down_sync(0xffffffffu, o, s);
    if ((j & 31) == 0) red[j >> 5] = o;
    __syncthreads();
    if (j == 0) out[g] = red[0] + red[1] + red[2] + red[3] + fb2[0];
}

// ---------------- launch ----------------
extern "C" void kernel_launch(void* const* d_in, const int* in_sizes, int n_in,
                              void* d_out, int out_size) {
    const float* x    = (const float*)d_in[0];
    const int*   ei   = (const int*)d_in[1];
    const float* ea   = (const float*)d_in[2];
    const int*   batch= (const int*)d_in[3];
    const float* W1   = (const float*)d_in[4];
    const float* b1   = (const float*)d_in[5];
    const float* W2   = (const float*)d_in[6];
    const float* b2   = (const float*)d_in[7];
    const float* fW1  = (const float*)d_in[8];
    const float* fb1  = (const float*)d_in[9];
    const float* fW2  = (const float*)d_in[10];
    const float* fb2  = (const float*)d_in[11];
    float* out = (float*)d_out;

    const int* src = ei;        // edge_index[0]
    const int* dst = ei + EE;   // edge_index[1]

    void *p0, *p1;
    cudaGetSymbolAddress(&p0, g_buf0);
    cudaGetSymbolAddress(&p1, g_buf1);
    float* buf0 = (float*)p0;
    float* buf1 = (float*)p1;

    const int tb = 256;
    init_kernel<<<(NN + tb - 1) / tb, tb>>>();
    count_kernel<<<(EE + tb - 1) / tb, tb>>>(dst, ea);
    scan_kernel<<<1, 1024>>>();
    scatter_kernel<<<(EE + tb - 1) / tb, tb>>>(src, dst, ea);
    dinv_kernel<<<(NN + tb - 1) / tb, tb>>>();

    dim3 ggrid((NN + BM - 1) / BM, HH / BN);
    gemm_kernel<<<ggrid, 256>>>(x, W1, buf0);                       // h1 = x @ W1^T
    agg_kernel<<<((NN * 32) + tb - 1) / tb, tb>>>(buf0, b1, buf1);  // relu(A_hat h1 + b1)
    gemm_kernel<<<ggrid, 256>>>(buf1, W2, buf0);                    // h2 = h @ W2^T
    agg_kernel<<<((NN * 32) + tb - 1) / tb, tb>>>(buf0, b2, buf1);  // relu(A_hat h2 + b2)

    int pwarps = (NN + CHUNK - 1) / CHUNK;
    pool_kernel<<<((pwarps * 32) + tb - 1) / tb, tb>>>(buf1, batch);
    mlp_kernel<<<GG, HH>>>(fW1, fb1, fW2, fb2, out);
}

// round 7
// speedup vs baseline: 1.6279x; 1.6279x over previous
#include <cuda_runtime.h>
#include <cuda_bf16.h>
#include <cstdint>

#define NN 50000
#define EE 500000
#define HH 128
#define GG 256

// ---------------- scratch (device globals; no allocs allowed) ----------------
static __device__ __align__(16) float g_buf0[(size_t)NN * HH];
static __device__ __align__(16) float g_buf1[(size_t)NN * HH];
static __device__ float g_deg[NN];
static __device__ float g_dinv[NN];
static __device__ float g_sn[NN];      // self-loop coeff = 1/deg
static __device__ int   g_cnt[NN];
static __device__ int   g_off[NN];
static __device__ int   g_part[256];   // scan partials
static __device__ int   g_pos[EE];
static __device__ int   g_csrc[EE];
static __device__ float g_cw[EE];      // CSR: PRE-NORMALIZED edge weight
static __device__ __align__(16) float g_pooled[GG * HH];
static __device__ float g_gcnt[GG];
// bf16 hi/lo weight images, plain row-major [128][128] (32KB each)
static __device__ __align__(16) unsigned char g_W1h[32768], g_W1l[32768];
static __device__ __align__(16) unsigned char g_W2h[32768], g_W2l[32768];

// ---------------- setup kernels ----------------
__global__ void init_kernel() {
    int i = blockIdx.x * blockDim.x + threadIdx.x;
    if (i < NN) { g_deg[i] = 1.0f; g_cnt[i] = 0; }
    if (i < GG * HH) g_pooled[i] = 0.0f;
    if (i < GG) g_gcnt[i] = 0.0f;
}

__global__ void count_kernel(const int* __restrict__ dst, const float* __restrict__ ew) {
    int e = blockIdx.x * blockDim.x + threadIdx.x;
    if (e >= EE) return;
    int d = dst[e];
    atomicAdd(&g_deg[d], ew[e]);
    g_pos[e] = atomicAdd(&g_cnt[d], 1);
}

// 3-phase exclusive scan of g_cnt -> g_off
__global__ void scan1_kernel() {        // 196 blocks x 256: block sums
    __shared__ int sh[256];
    int t = threadIdx.x;
    int i = blockIdx.x * 256 + t;
    sh[t] = (i < NN) ? g_cnt[i] : 0;
    __syncthreads();
    #pragma unroll
    for (int s = 128; s > 0; s >>= 1) {
        if (t < s) sh[t] += sh[t + s];
        __syncthreads();
    }
    if (t == 0) g_part[blockIdx.x] = sh[0];
}
__global__ void scan2_kernel() {        // 1 block x 256: exclusive scan of partials
    __shared__ int sh[256];
    int t = threadIdx.x;
    int nb = (NN + 255) / 256;
    int v = (t < nb) ? g_part[t] : 0;
    sh[t] = v;
    __syncthreads();
    #pragma unroll
    for (int s = 1; s < 256; s <<= 1) {
        int u = (t >= s) ? sh[t - s] : 0;
        __syncthreads();
        sh[t] += u;
        __syncthreads();
    }
    g_part[t] = sh[t] - v;
}
__global__ void scan3_kernel() {        // 196 blocks x 256: local scan + base
    __shared__ int sh[256];
    int t = threadIdx.x;
    int i = blockIdx.x * 256 + t;
    int v = (i < NN) ? g_cnt[i] : 0;
    sh[t] = v;
    __syncthreads();
    #pragma unroll
    for (int s = 1; s < 256; s <<= 1) {
        int u = (t >= s) ? sh[t - s] : 0;
        __syncthreads();
        sh[t] += u;
        __syncthreads();
    }
    if (i < NN) g_off[i] = g_part[blockIdx.x] + sh[t] - v;
}

__global__ void dinv_kernel() {
    int i = blockIdx.x * blockDim.x + threadIdx.x;
    if (i < NN) {
        float d = rsqrtf(g_deg[i]);   // deg >= 1 always
        g_dinv[i] = d;
        g_sn[i] = d * d;
    }
}

__global__ void scatter_kernel(const int* __restrict__ src, const int* __restrict__ dst,
                               const float* __restrict__ ew) {
    int e = blockIdx.x * blockDim.x + threadIdx.x;
    if (e >= EE) return;
    int d = dst[e];
    int s = src[e];
    int idx = g_off[d] + g_pos[e];
    g_csrc[idx] = s;
    g_cw[idx] = g_dinv[s] * ew[e] * g_dinv[d];   // pre-normalized
}

// ---------------- weight conversion: fp32 -> bf16 hi/lo, row-major ------------
__global__ void convw_kernel(const float* __restrict__ W1, const float* __restrict__ W2) {
    const float* W = blockIdx.x ? W2 : W1;
    unsigned char* oh = blockIdx.x ? g_W2h : g_W1h;
    unsigned char* ol = blockIdx.x ? g_W2l : g_W1l;
    int r = threadIdx.x;   // 128 threads, one row each
    for (int c = 0; c < HH; c += 2) {
        float a0 = W[r * HH + c], a1 = W[r * HH + c + 1];
        __nv_bfloat16 h0 = __float2bfloat16(a0), h1 = __float2bfloat16(a1);
        __nv_bfloat16 l0 = __float2bfloat16(a0 - __bfloat162float(h0));
        __nv_bfloat16 l1 = __float2bfloat16(a1 - __bfloat162float(h1));
        uint32_t off = (uint32_t)(r * HH + c) * 2;
        *(uint32_t*)(oh + off) = ((uint32_t)__bfloat16_as_ushort(h1) << 16) | __bfloat16_as_ushort(h0);
        *(uint32_t*)(ol + off) = ((uint32_t)__bfloat16_as_ushort(l1) << 16) | __bfloat16_as_ushort(l0);
    }
}

// ---------------- HMMA GEMM: C[NN x 128] = A[NN x 128] @ W^T ------------------
// bf16 split: C = Ah*Wh + Ah*Wl + Al*Wh, fp32 register accumulators.
// SMEM: bf16 tiles [128][136] (136-pad -> conflict-free fragment lds).
#define SROW 136
#define TILE_B ((size_t)128 * SROW * 2)        // 34816 bytes
#define OA_H 0
#define OA_L (1 * 34816)
#define OW_H (2 * 34816)
#define OW_L (3 * 34816)
#define GSMEM_BYTES (4 * 34816)                // 139264

__device__ __forceinline__ void mma_bf16(float* c, const uint32_t* a, const uint32_t* b) {
    asm volatile(
        "mma.sync.aligned.m16n8k16.row.col.f32.bf16.bf16.f32 "
        "{%0,%1,%2,%3}, {%4,%5,%6,%7}, {%8,%9}, {%0,%1,%2,%3};"
        : "+f"(c[0]), "+f"(c[1]), "+f"(c[2]), "+f"(c[3])
        : "r"(a[0]), "r"(a[1]), "r"(a[2]), "r"(a[3]), "r"(b[0]), "r"(b[1]));
}

__global__ void __launch_bounds__(256) gemm_mma_kernel(
    const float* __restrict__ A,
    const unsigned char* __restrict__ Wh,
    const unsigned char* __restrict__ Wl,
    float* __restrict__ C
) {
    extern __shared__ __align__(16) unsigned char smem[];
    int t = threadIdx.x;
    int rowBase = blockIdx.x * 128;

    // ---- prologue: A fp32 -> bf16 hi/lo into padded smem ----
    #pragma unroll
    for (int i = 0; i < 16; i++) {
        int idx = t + i * 256;              // 0..4095
        int row = idx >> 5;                 // 0..127
        int col = (idx & 31) << 2;          // 0..124 step 4
        float4 v = make_float4(0.f, 0.f, 0.f, 0.f);
        int gr = rowBase + row;
        if (gr < NN) v = *(const float4*)(A + (size_t)gr * HH + col);
        __nv_bfloat16 h0 = __float2bfloat16(v.x), h1 = __float2bfloat16(v.y);
        __nv_bfloat16 h2 = __float2bfloat16(v.z), h3 = __float2bfloat16(v.w);
        __nv_bfloat16 l0 = __float2bfloat16(v.x - __bfloat162float(h0));
        __nv_bfloat16 l1 = __float2bfloat16(v.y - __bfloat162float(h1));
        __nv_bfloat16 l2 = __float2bfloat16(v.z - __bfloat162float(h2));
        __nv_bfloat16 l3 = __float2bfloat16(v.w - __bfloat162float(h3));
        uint32_t off = (uint32_t)(row * SROW + col) * 2;
        uint2 ph, pl;
        ph.x = ((uint32_t)__bfloat16_as_ushort(h1) << 16) | __bfloat16_as_ushort(h0);
        ph.y = ((uint32_t)__bfloat16_as_ushort(h3) << 16) | __bfloat16_as_ushort(h2);
        pl.x = ((uint32_t)__bfloat16_as_ushort(l1) << 16) | __bfloat16_as_ushort(l0);
        pl.y = ((uint32_t)__bfloat16_as_ushort(l3) << 16) | __bfloat16_as_ushort(l2);
        *(uint2*)(smem + OA_H + off) = ph;
        *(uint2*)(smem + OA_L + off) = pl;
    }
    // ---- copy W hi/lo (row-major bf16) into padded smem ----
    {
        const uint2* gh = (const uint2*)Wh;   // 4096 uint2 (4 bf16 each)
        const uint2* gl = (const uint2*)Wl;
        #pragma unroll
        for (int i = 0; i < 16; i++) {
            int idx = t + i * 256;
            int row = idx >> 5;
            int col = (idx & 31) << 2;
            uint32_t off = (uint32_t)(row * SROW + col) * 2;
            *(uint2*)(smem + OW_H + off) = gh[idx];
            *(uint2*)(smem + OW_L + off) = gl[idx];
        }
    }
    __syncthreads();

    // ---- main: 8 warps, each computes 32 rows x 64 cols ----
    int warp = t >> 5, lane = t & 31;
    int mrow = (warp >> 1) * 32;         // 0/32/64/96
    int ncol = (warp & 1) * 64;          // 0/64
    int qrow = lane >> 2, qp = lane & 3;

    float acc[2][8][4];
    #pragma unroll
    for (int mt = 0; mt < 2; mt++)
        #pragma unroll
        for (int nt = 0; nt < 8; nt++)
            #pragma unroll
            for (int q = 0; q < 4; q++) acc[mt][nt][q] = 0.f;

    #pragma unroll
    for (int k0 = 0; k0 < HH; k0 += 16) {
        int cb = k0 + qp * 2;
        uint32_t ah[2][4], al[2][4], wh[8][2], wl[8][2];
        #pragma unroll
        for (int mt = 0; mt < 2; mt++) {
            int r = mrow + mt * 16 + qrow;
            uint32_t o00 = (uint32_t)(r * SROW + cb) * 2;
            uint32_t o10 = o00 + 8u * SROW * 2;
            ah[mt][0] = *(const uint32_t*)(smem + OA_H + o00);
            ah[mt][1] = *(const uint32_t*)(smem + OA_H + o10);
            ah[mt][2] = *(const uint32_t*)(smem + OA_H + o00 + 16);
            ah[mt][3] = *(const uint32_t*)(smem + OA_H + o10 + 16);
            al[mt][0] = *(const uint32_t*)(smem + OA_L + o00);
            al[mt][1] = *(const uint32_t*)(smem + OA_L + o10);
            al[mt][2] = *(const uint32_t*)(smem + OA_L + o00 + 16);
            al[mt][3] = *(const uint32_t*)(smem + OA_L + o10 + 16);
        }
        #pragma unroll
        for (int nt = 0; nt < 8; nt++) {
            int n = ncol + nt * 8 + qrow;
            uint32_t o = (uint32_t)(n * SROW + cb) * 2;
            wh[nt][0] = *(const uint32_t*)(smem + OW_H + o);
            wh[nt][1] = *(const uint32_t*)(smem + OW_H + o + 16);
            wl[nt][0] = *(const uint32_t*)(smem + OW_L + o);
            wl[nt][1] = *(const uint32_t*)(smem + OW_L + o + 16);
        }
        #pragma unroll
        for (int mt = 0; mt < 2; mt++)
            #pragma unroll
            for (int nt = 0; nt < 8; nt++) {
                mma_bf16(acc[mt][nt], ah[mt], wh[nt]);
                mma_bf16(acc[mt][nt], ah[mt], wl[nt]);
                mma_bf16(acc[mt][nt], al[mt], wh[nt]);
            }
    }

    // ---- store ----
    #pragma unroll
    for (int mt = 0; mt < 2; mt++) {
        int r0 = rowBase + mrow + mt * 16 + qrow;
        #pragma unroll
        for (int nt = 0; nt < 8; nt++) {
            int cc = ncol + nt * 8 + qp * 2;
            if (r0 < NN)
                *(float2*)(C + (size_t)r0 * HH + cc) = make_float2(acc[mt][nt][0], acc[mt][nt][1]);
            if (r0 + 8 < NN)
                *(float2*)(C + (size_t)(r0 + 8) * HH + cc) = make_float2(acc[mt][nt][2], acc[mt][nt][3]);
        }
    }
}

// ---------------- aggregation: out[n] = relu(h[n]/deg + sum h[s]*norm + b) ------
__global__ void agg_kernel(const float* __restrict__ h, const float* __restrict__ bias,
                           float* __restrict__ out) {
    int w = (blockIdx.x * blockDim.x + threadIdx.x) >> 5;
    int lane = threadIdx.x & 31;
    if (w >= NN) return;
    int n = w;
    float sn = g_sn[n];
    float4 hv = *reinterpret_cast<const float4*>(h + (size_t)n * HH + (lane << 2));
    float4 acc = make_float4(hv.x * sn, hv.y * sn, hv.z * sn, hv.w * sn);
    int o = g_off[n], c = g_cnt[n];
    for (int j = 0; j < c; j++) {
        int s = g_csrc[o + j];
        float nr = g_cw[o + j];
        float4 v = *reinterpret_cast<const float4*>(h + (size_t)s * HH + (lane << 2));
        acc.x += v.x * nr; acc.y += v.y * nr; acc.z += v.z * nr; acc.w += v.w * nr;
    }
    float4 b = *reinterpret_cast<const float4*>(bias + (lane << 2));
    float4 r = make_float4(fmaxf(acc.x + b.x, 0.f), fmaxf(acc.y + b.y, 0.f),
                           fmaxf(acc.z + b.z, 0.f), fmaxf(acc.w + b.w, 0.f));
    *reinterpret_cast<float4*>(out + (size_t)n * HH + (lane << 2)) = r;
}

// ---------------- pooling (batch sorted; run-accumulate + atomic flush) ---------
#define CHUNK 32
__global__ void pool_kernel(const float* __restrict__ h, const int* __restrict__ batch) {
    int w = (blockIdx.x * blockDim.x + threadIdx.x) >> 5;
    int lane = threadIdx.x & 31;
    int start = w * CHUNK;
    if (start >= NN) return;
    int end = min(NN, start + CHUNK);
    int cur = batch[start];
    float4 acc = make_float4(0.f, 0.f, 0.f, 0.f);
    float cnt = 0.f;
    for (int i = start; i < end; i++) {
        int g = batch[i];
        if (g != cur) {
            float* p = &g_pooled[(size_t)cur * HH + (lane << 2)];
            atomicAdd(p + 0, acc.x); atomicAdd(p + 1, acc.y);
            atomicAdd(p + 2, acc.z); atomicAdd(p + 3, acc.w);
            if (lane == 0) atomicAdd(&g_gcnt[cur], cnt);
            acc = make_float4(0.f, 0.f, 0.f, 0.f); cnt = 0.f; cur = g;
        }
        float4 v = *reinterpret_cast<const float4*>(h + (size_t)i * HH + (lane << 2));
        acc.x += v.x; acc.y += v.y; acc.z += v.z; acc.w += v.w;
        cnt += 1.f;
    }
    float* p = &g_pooled[(size_t)cur * HH + (lane << 2)];
    atomicAdd(p + 0, acc.x); atomicAdd(p + 1, acc.y);
    atomicAdd(p + 2, acc.z); atomicAdd(p + 3, acc.w);
    if (lane == 0) atomicAdd(&g_gcnt[cur], cnt);
}

// ---------------- head MLP ----------------
__global__ void mlp_kernel(const float* __restrict__ fW1, const float* __restrict__ fb1,
                           const float* __restrict__ fW2, const float* __restrict__ fb2,
                           float* __restrict__ out) {
    __shared__ float p[HH];
    __shared__ float red[4];
    int g = blockIdx.x, j = threadIdx.x;
    float c = fmaxf(g_gcnt[g], 1.0f);
    p[j] = g_pooled[(size_t)g * HH + j] / c;
    __syncthreads();
    float acc = fb1[j];
    #pragma unroll 8
    for (int k = 0; k < HH; k++) acc += p[k] * fW1[(size_t)j * HH + k];
    float o = fmaxf(acc, 0.f) * fW2[j];
    #pragma unroll
    for (int s = 16; s > 0; s >>= 1) o += __shfl_down_sync(0xffffffffu, o, s);
    if ((j & 31) == 0) red[j >> 5] = o;
    __syncthreads();
    if (j == 0) out[g] = red[0] + red[1] + red[2] + red[3] + fb2[0];
}

// ---------------- launch ----------------
extern "C" void kernel_launch(void* const* d_in, const int* in_sizes, int n_in,
                              void* d_out, int out_size) {
    const float* x     = (const float*)d_in[0];
    const int*   ei    = (const int*)d_in[1];
    const float* ea    = (const float*)d_in[2];
    const int*   batch = (const int*)d_in[3];
    const float* W1    = (const float*)d_in[4];
    const float* b1    = (const float*)d_in[5];
    const float* W2    = (const float*)d_in[6];
    const float* b2    = (const float*)d_in[7];
    const float* fW1   = (const float*)d_in[8];
    const float* fb1   = (const float*)d_in[9];
    const float* fW2   = (const float*)d_in[10];
    const float* fb2   = (const float*)d_in[11];
    float* out = (float*)d_out;

    const int* src = ei;
    const int* dst = ei + EE;

    void *p0, *p1, *pw1h, *pw1l, *pw2h, *pw2l;
    cudaGetSymbolAddress(&p0, g_buf0);
    cudaGetSymbolAddress(&p1, g_buf1);
    cudaGetSymbolAddress(&pw1h, g_W1h);
    cudaGetSymbolAddress(&pw1l, g_W1l);
    cudaGetSymbolAddress(&pw2h, g_W2h);
    cudaGetSymbolAddress(&pw2l, g_W2l);
    float* buf0 = (float*)p0;
    float* buf1 = (float*)p1;

    cudaFuncSetAttribute(gemm_mma_kernel, cudaFuncAttributeMaxDynamicSharedMemorySize, GSMEM_BYTES);

    const int tb = 256;
    const int nblk = (NN + tb - 1) / tb;    // 196
    const int eblk = (EE + tb - 1) / tb;    // 1954

    convw_kernel<<<2, 128>>>(W1, W2);
    init_kernel<<<nblk, tb>>>();
    count_kernel<<<eblk, tb>>>(dst, ea);
    scan1_kernel<<<nblk, tb>>>();
    scan2_kernel<<<1, 256>>>();
    scan3_kernel<<<nblk, tb>>>();
    dinv_kernel<<<nblk, tb>>>();
    scatter_kernel<<<eblk, tb>>>(src, dst, ea);

    const int ggrid = (NN + 127) / 128;     // 391
    gemm_mma_kernel<<<ggrid, 256, GSMEM_BYTES>>>(x, (const unsigned char*)pw1h,
                                                 (const unsigned char*)pw1l, buf0);
    agg_kernel<<<((NN * 32) + tb - 1) / tb, tb>>>(buf0, b1, buf1);
    gemm_mma_kernel<<<ggrid, 256, GSMEM_BYTES>>>(buf1, (const unsigned char*)pw2h,
                                                 (const unsigned char*)pw2l, buf0);
    agg_kernel<<<((NN * 32) + tb - 1) / tb, tb>>>(buf0, b2, buf1);

    int pwarps = (NN + CHUNK - 1) / CHUNK;
    pool_kernel<<<((pwarps * 32) + tb - 1) / tb, tb>>>(buf1, batch);
    mlp_kernel<<<GG, HH>>>(fW1, fb1, fW2, fb2, out);
}

// round 8
// speedup vs baseline: 1.7139x; 1.0528x over previous
#include <cuda_runtime.h>
#include <cuda_bf16.h>
#include <cstdint>

#define NN 50000
#define EE 500000
#define HH 128
#define GG 256

// ---------------- scratch (device globals; no allocs allowed) ----------------
static __device__ __align__(16) float g_buf0[(size_t)NN * HH];
static __device__ __align__(16) float g_buf1[(size_t)NN * HH];
static __device__ float g_deg[NN];
static __device__ float g_dinv[NN];
static __device__ float g_sn[NN];      // self-loop coeff = 1/deg
static __device__ int   g_cnt[NN];
static __device__ int   g_off[NN];
static __device__ int   g_part[256];   // scan partials
static __device__ int   g_pos[EE];
static __device__ __align__(8) int2 g_edge[EE];   // CSR: {src, normalized w as bits}
static __device__ __align__(16) float g_pooled[GG * HH];
static __device__ float g_gcnt[GG];
// bf16 hi/lo weight images, plain row-major [128][128] (32KB each)
static __device__ __align__(16) unsigned char g_W1h[32768], g_W1l[32768];
static __device__ __align__(16) unsigned char g_W2h[32768], g_W2l[32768];

// ---------------- fused setup: init state + convert weights ------------------
// blocks 0..195: per-node/per-graph init.  blocks 196,197: W1/W2 fp32->bf16 hi/lo.
__global__ void setup_kernel(const float* __restrict__ W1, const float* __restrict__ W2) {
    int blk = blockIdx.x, t = threadIdx.x;
    int i = blk * 256 + t;
    if (i < NN) { g_deg[i] = 1.0f; g_cnt[i] = 0; }
    if (i < GG * HH) g_pooled[i] = 0.0f;
    if (i < GG) g_gcnt[i] = 0.0f;
    if (blk >= 196) {
        const float* W = (blk == 197) ? W2 : W1;
        unsigned char* oh = (blk == 197) ? g_W2h : g_W1h;
        unsigned char* ol = (blk == 197) ? g_W2l : g_W1l;
        int r = t >> 1;                    // 0..127
        int c0 = (t & 1) * 64;             // 0 or 64
        for (int c = c0; c < c0 + 64; c += 2) {
            float a0 = W[r * HH + c], a1 = W[r * HH + c + 1];
            __nv_bfloat16 h0 = __float2bfloat16(a0), h1 = __float2bfloat16(a1);
            __nv_bfloat16 l0 = __float2bfloat16(a0 - __bfloat162float(h0));
            __nv_bfloat16 l1 = __float2bfloat16(a1 - __bfloat162float(h1));
            uint32_t off = (uint32_t)(r * HH + c) * 2;
            *(uint32_t*)(oh + off) = ((uint32_t)__bfloat16_as_ushort(h1) << 16) | __bfloat16_as_ushort(h0);
            *(uint32_t*)(ol + off) = ((uint32_t)__bfloat16_as_ushort(l1) << 16) | __bfloat16_as_ushort(l0);
        }
    }
}

__global__ void count_kernel(const int* __restrict__ dst, const float* __restrict__ ew) {
    int e = blockIdx.x * blockDim.x + threadIdx.x;
    if (e >= EE) return;
    int d = dst[e];
    atomicAdd(&g_deg[d], ew[e]);
    g_pos[e] = atomicAdd(&g_cnt[d], 1);
}

// 3-phase exclusive scan of g_cnt -> g_off (+ dinv fused into phase 3)
__global__ void scan1_kernel() {        // 196 blocks x 256: block sums
    __shared__ int sh[256];
    int t = threadIdx.x;
    int i = blockIdx.x * 256 + t;
    sh[t] = (i < NN) ? g_cnt[i] : 0;
    __syncthreads();
    #pragma unroll
    for (int s = 128; s > 0; s >>= 1) {
        if (t < s) sh[t] += sh[t + s];
        __syncthreads();
    }
    if (t == 0) g_part[blockIdx.x] = sh[0];
}
__global__ void scan2_kernel() {        // 1 block x 256: exclusive scan of partials
    __shared__ int sh[256];
    int t = threadIdx.x;
    int nb = (NN + 255) / 256;
    int v = (t < nb) ? g_part[t] : 0;
    sh[t] = v;
    __syncthreads();
    #pragma unroll
    for (int s = 1; s < 256; s <<= 1) {
        int u = (t >= s) ? sh[t - s] : 0;
        __syncthreads();
        sh[t] += u;
        __syncthreads();
    }
    g_part[t] = sh[t] - v;
}
__global__ void scan3_kernel() {        // 196 blocks x 256: local scan + base + dinv
    __shared__ int sh[256];
    int t = threadIdx.x;
    int i = blockIdx.x * 256 + t;
    int v = (i < NN) ? g_cnt[i] : 0;
    sh[t] = v;
    __syncthreads();
    #pragma unroll
    for (int s = 1; s < 256; s <<= 1) {
        int u = (t >= s) ? sh[t - s] : 0;
        __syncthreads();
        sh[t] += u;
        __syncthreads();
    }
    if (i < NN) {
        g_off[i] = g_part[blockIdx.x] + sh[t] - v;
        float d = rsqrtf(g_deg[i]);   // deg >= 1 always
        g_dinv[i] = d;
        g_sn[i] = d * d;
    }
}

__global__ void scatter_kernel(const int* __restrict__ src, const int* __restrict__ dst,
                               const float* __restrict__ ew) {
    int e = blockIdx.x * blockDim.x + threadIdx.x;
    if (e >= EE) return;
    int d = dst[e];
    int s = src[e];
    int idx = g_off[d] + g_pos[e];
    float w = g_dinv[s] * ew[e] * g_dinv[d];   // pre-normalized
    g_edge[idx] = make_int2(s, __float_as_int(w));
}

// ---------------- HMMA GEMM: C[NN x 128] = A[NN x 128] @ W^T ------------------
// bf16 split: C = Ah*Wh + Ah*Wl + Al*Wh, fp32 register accumulators.
#define SROW 136
#define OA_H 0
#define OA_L (1 * 34816)
#define OW_H (2 * 34816)
#define OW_L (3 * 34816)
#define GSMEM_BYTES (4 * 34816)                // 139264

__device__ __forceinline__ void mma_bf16(float* c, const uint32_t* a, const uint32_t* b) {
    asm volatile(
        "mma.sync.aligned.m16n8k16.row.col.f32.bf16.bf16.f32 "
        "{%0,%1,%2,%3}, {%4,%5,%6,%7}, {%8,%9}, {%0,%1,%2,%3};"
        : "+f"(c[0]), "+f"(c[1]), "+f"(c[2]), "+f"(c[3])
        : "r"(a[0]), "r"(a[1]), "r"(a[2]), "r"(a[3]), "r"(b[0]), "r"(b[1]));
}

__global__ void __launch_bounds__(256) gemm_mma_kernel(
    const float* __restrict__ A,
    const unsigned char* __restrict__ Wh,
    const unsigned char* __restrict__ Wl,
    float* __restrict__ C
) {
    extern __shared__ __align__(16) unsigned char smem[];
    int t = threadIdx.x;
    int rowBase = blockIdx.x * 128;

    #pragma unroll
    for (int i = 0; i < 16; i++) {
        int idx = t + i * 256;
        int row = idx >> 5;
        int col = (idx & 31) << 2;
        float4 v = make_float4(0.f, 0.f, 0.f, 0.f);
        int gr = rowBase + row;
        if (gr < NN) v = *(const float4*)(A + (size_t)gr * HH + col);
        __nv_bfloat16 h0 = __float2bfloat16(v.x), h1 = __float2bfloat16(v.y);
        __nv_bfloat16 h2 = __float2bfloat16(v.z), h3 = __float2bfloat16(v.w);
        __nv_bfloat16 l0 = __float2bfloat16(v.x - __bfloat162float(h0));
        __nv_bfloat16 l1 = __float2bfloat16(v.y - __bfloat162float(h1));
        __nv_bfloat16 l2 = __float2bfloat16(v.z - __bfloat162float(h2));
        __nv_bfloat16 l3 = __float2bfloat16(v.w - __bfloat162float(h3));
        uint32_t off = (uint32_t)(row * SROW + col) * 2;
        uint2 ph, pl;
        ph.x = ((uint32_t)__bfloat16_as_ushort(h1) << 16) | __bfloat16_as_ushort(h0);
        ph.y = ((uint32_t)__bfloat16_as_ushort(h3) << 16) | __bfloat16_as_ushort(h2);
        pl.x = ((uint32_t)__bfloat16_as_ushort(l1) << 16) | __bfloat16_as_ushort(l0);
        pl.y = ((uint32_t)__bfloat16_as_ushort(l3) << 16) | __bfloat16_as_ushort(l2);
        *(uint2*)(smem + OA_H + off) = ph;
        *(uint2*)(smem + OA_L + off) = pl;
    }
    {
        const uint2* gh = (const uint2*)Wh;
        const uint2* gl = (const uint2*)Wl;
        #pragma unroll
        for (int i = 0; i < 16; i++) {
            int idx = t + i * 256;
            int row = idx >> 5;
            int col = (idx & 31) << 2;
            uint32_t off = (uint32_t)(row * SROW + col) * 2;
            *(uint2*)(smem + OW_H + off) = gh[idx];
            *(uint2*)(smem + OW_L + off) = gl[idx];
        }
    }
    __syncthreads();

    int warp = t >> 5, lane = t & 31;
    int mrow = (warp >> 1) * 32;
    int ncol = (warp & 1) * 64;
    int qrow = lane >> 2, qp = lane & 3;

    float acc[2][8][4];
    #pragma unroll
    for (int mt = 0; mt < 2; mt++)
        #pragma unroll
        for (int nt = 0; nt < 8; nt++)
            #pragma unroll
            for (int q = 0; q < 4; q++) acc[mt][nt][q] = 0.f;

    #pragma unroll
    for (int k0 = 0; k0 < HH; k0 += 16) {
        int cb = k0 + qp * 2;
        uint32_t ah[2][4], al[2][4], wh[8][2], wl[8][2];
        #pragma unroll
        for (int mt = 0; mt < 2; mt++) {
            int r = mrow + mt * 16 + qrow;
            uint32_t o00 = (uint32_t)(r * SROW + cb) * 2;
            uint32_t o10 = o00 + 8u * SROW * 2;
            ah[mt][0] = *(const uint32_t*)(smem + OA_H + o00);
            ah[mt][1] = *(const uint32_t*)(smem + OA_H + o10);
            ah[mt][2] = *(const uint32_t*)(smem + OA_H + o00 + 16);
            ah[mt][3] = *(const uint32_t*)(smem + OA_H + o10 + 16);
            al[mt][0] = *(const uint32_t*)(smem + OA_L + o00);
            al[mt][1] = *(const uint32_t*)(smem + OA_L + o10);
            al[mt][2] = *(const uint32_t*)(smem + OA_L + o00 + 16);
            al[mt][3] = *(const uint32_t*)(smem + OA_L + o10 + 16);
        }
        #pragma unroll
        for (int nt = 0; nt < 8; nt++) {
            int n = ncol + nt * 8 + qrow;
            uint32_t o = (uint32_t)(n * SROW + cb) * 2;
            wh[nt][0] = *(const uint32_t*)(smem + OW_H + o);
            wh[nt][1] = *(const uint32_t*)(smem + OW_H + o + 16);
            wl[nt][0] = *(const uint32_t*)(smem + OW_L + o);
            wl[nt][1] = *(const uint32_t*)(smem + OW_L + o + 16);
        }
        #pragma unroll
        for (int mt = 0; mt < 2; mt++)
            #pragma unroll
            for (int nt = 0; nt < 8; nt++) {
                mma_bf16(acc[mt][nt], ah[mt], wh[nt]);
                mma_bf16(acc[mt][nt], ah[mt], wl[nt]);
                mma_bf16(acc[mt][nt], al[mt], wh[nt]);
            }
    }

    #pragma unroll
    for (int mt = 0; mt < 2; mt++) {
        int r0 = rowBase + mrow + mt * 16 + qrow;
        #pragma unroll
        for (int nt = 0; nt < 8; nt++) {
            int cc = ncol + nt * 8 + qp * 2;
            if (r0 < NN)
                *(float2*)(C + (size_t)r0 * HH + cc) = make_float2(acc[mt][nt][0], acc[mt][nt][1]);
            if (r0 + 8 < NN)
                *(float2*)(C + (size_t)(r0 + 8) * HH + cc) = make_float2(acc[mt][nt][2], acc[mt][nt][3]);
        }
    }
}

// ---------------- aggregation: out[n] = relu(h[n]/deg + sum h[s]*norm + b) ------
__global__ void agg_kernel(const float* __restrict__ h, const float* __restrict__ bias,
                           float* __restrict__ out) {
    int w = (blockIdx.x * blockDim.x + threadIdx.x) >> 5;
    int lane = threadIdx.x & 31;
    if (w >= NN) return;
    int n = w;
    float sn = g_sn[n];
    float4 hv = *reinterpret_cast<const float4*>(h + (size_t)n * HH + (lane << 2));
    float4 acc = make_float4(hv.x * sn, hv.y * sn, hv.z * sn, hv.w * sn);
    int o = g_off[n], c = g_cnt[n];
    const int2* ep = g_edge + o;
    for (int j = 0; j < c; j++) {
        int2 e = ep[j];
        float nr = __int_as_float(e.y);
        float4 v = *reinterpret_cast<const float4*>(h + (size_t)e.x * HH + (lane << 2));
        acc.x += v.x * nr; acc.y += v.y * nr; acc.z += v.z * nr; acc.w += v.w * nr;
    }
    float4 b = *reinterpret_cast<const float4*>(bias + (lane << 2));
    float4 r = make_float4(fmaxf(acc.x + b.x, 0.f), fmaxf(acc.y + b.y, 0.f),
                           fmaxf(acc.z + b.z, 0.f), fmaxf(acc.w + b.w, 0.f));
    *reinterpret_cast<float4*>(out + (size_t)n * HH + (lane << 2)) = r;
}

// ---------------- pooling (batch sorted; run-accumulate + atomic flush) ---------
#define CHUNK 32
__global__ void pool_kernel(const float* __restrict__ h, const int* __restrict__ batch) {
    int w = (blockIdx.x * blockDim.x + threadIdx.x) >> 5;
    int lane = threadIdx.x & 31;
    int start = w * CHUNK;
    if (start >= NN) return;
    int end = min(NN, start + CHUNK);
    int cur = batch[start];
    float4 acc = make_float4(0.f, 0.f, 0.f, 0.f);
    float cnt = 0.f;
    for (int i = start; i < end; i++) {
        int g = batch[i];
        if (g != cur) {
            float* p = &g_pooled[(size_t)cur * HH + (lane << 2)];
            atomicAdd(p + 0, acc.x); atomicAdd(p + 1, acc.y);
            atomicAdd(p + 2, acc.z); atomicAdd(p + 3, acc.w);
            if (lane == 0) atomicAdd(&g_gcnt[cur], cnt);
            acc = make_float4(0.f, 0.f, 0.f, 0.f); cnt = 0.f; cur = g;
        }
        float4 v = *reinterpret_cast<const float4*>(h + (size_t)i * HH + (lane << 2));
        acc.x += v.x; acc.y += v.y; acc.z += v.z; acc.w += v.w;
        cnt += 1.f;
    }
    float* p = &g_pooled[(size_t)cur * HH + (lane << 2)];
    atomicAdd(p + 0, acc.x); atomicAdd(p + 1, acc.y);
    atomicAdd(p + 2, acc.z); atomicAdd(p + 3, acc.w);
    if (lane == 0) atomicAdd(&g_gcnt[cur], cnt);
}

// ---------------- head MLP ----------------
__global__ void mlp_kernel(const float* __restrict__ fW1, const float* __restrict__ fb1,
                           const float* __restrict__ fW2, const float* __restrict__ fb2,
                           float* __restrict__ out) {
    __shared__ float p[HH];
    __shared__ float red[4];
    int g = blockIdx.x, j = threadIdx.x;
    float c = fmaxf(g_gcnt[g], 1.0f);
    p[j] = g_pooled[(size_t)g * HH + j] / c;
    __syncthreads();
    float acc = fb1[j];
    #pragma unroll 8
    for (int k = 0; k < HH; k++) acc += p[k] * fW1[(size_t)j * HH + k];
    float o = fmaxf(acc, 0.f) * fW2[j];
    #pragma unroll
    for (int s = 16; s > 0; s >>= 1) o += __shfl_down_sync(0xffffffffu, o, s);
    if ((j & 31) == 0) red[j >> 5] = o;
    __syncthreads();
    if (j == 0) out[g] = red[0] + red[1] + red[2] + red[3] + fb2[0];
}

// ---------------- launch ----------------
extern "C" void kernel_launch(void* const* d_in, const int* in_sizes, int n_in,
                              void* d_out, int out_size) {
    const float* x     = (const float*)d_in[0];
    const int*   ei    = (const int*)d_in[1];
    const float* ea    = (const float*)d_in[2];
    const int*   batch = (const int*)d_in[3];
    const float* W1    = (const float*)d_in[4];
    const float* b1    = (const float*)d_in[5];
    const float* W2    = (const float*)d_in[6];
    const float* b2    = (const float*)d_in[7];
    const float* fW1   = (const float*)d_in[8];
    const float* fb1   = (const float*)d_in[9];
    const float* fW2   = (const float*)d_in[10];
    const float* fb2   = (const float*)d_in[11];
    float* out = (float*)d_out;

    const int* src = ei;
    const int* dst = ei + EE;

    void *p0, *p1, *pw1h, *pw1l, *pw2h, *pw2l;
    cudaGetSymbolAddress(&p0, g_buf0);
    cudaGetSymbolAddress(&p1, g_buf1);
    cudaGetSymbolAddress(&pw1h, g_W1h);
    cudaGetSymbolAddress(&pw1l, g_W1l);
    cudaGetSymbolAddress(&pw2h, g_W2h);
    cudaGetSymbolAddress(&pw2l, g_W2l);
    float* buf0 = (float*)p0;
    float* buf1 = (float*)p1;

    cudaFuncSetAttribute(gemm_mma_kernel, cudaFuncAttributeMaxDynamicSharedMemorySize, GSMEM_BYTES);

    const int tb = 256;
    const int nblk = (NN + tb - 1) / tb;    // 196
    const int eblk = (EE + tb - 1) / tb;    // 1954
    const int ggrid = (NN + 127) / 128;     // 391

    // fork-join: CSR build (s2) concurrent with GEMM1 (main stream).
    // No statics, no frees of in-capture resources; fall back to serial on failure.
    cudaStream_t s2 = 0;
    cudaEvent_t evA = 0, evB = 0;
    bool par = (cudaStreamCreateWithFlags(&s2, cudaStreamNonBlocking) == cudaSuccess);
    if (par) par = (cudaEventCreateWithFlags(&evA, cudaEventDisableTiming) == cudaSuccess);
    if (par) par = (cudaEventCreateWithFlags(&evB, cudaEventDisableTiming) == cudaSuccess);
    cudaStream_t sc = par ? s2 : (cudaStream_t)0;

    setup_kernel<<<198, 256>>>(W1, W2);
    if (par) {
        cudaEventRecord(evA, 0);
        cudaStreamWaitEvent(s2, evA, 0);
    }
    // CSR branch (on sc)
    count_kernel<<<eblk, tb, 0, sc>>>(dst, ea);
    scan1_kernel<<<nblk, tb, 0, sc>>>();
    scan2_kernel<<<1, 256, 0, sc>>>();
    scan3_kernel<<<nblk, tb, 0, sc>>>();
    scatter_kernel<<<eblk, tb, 0, sc>>>(src, dst, ea);
    // GEMM1 branch (main stream)
    gemm_mma_kernel<<<ggrid, 256, GSMEM_BYTES>>>(x, (const unsigned char*)pw1h,
                                                 (const unsigned char*)pw1l, buf0);
    if (par) {
        cudaEventRecord(evB, s2);
        cudaStreamWaitEvent(0, evB, 0);
    }

    agg_kernel<<<((NN * 32) + tb - 1) / tb, tb>>>(buf0, b1, buf1);
    gemm_mma_kernel<<<ggrid, 256, GSMEM_BYTES>>>(buf1, (const unsigned char*)pw2h,
                                                 (const unsigned char*)pw2l, buf0);
    agg_kernel<<<((NN * 32) + tb - 1) / tb, tb>>>(buf0, b2, buf1);

    int pwarps = (NN + CHUNK - 1) / CHUNK;
    pool_kernel<<<((pwarps * 32) + tb - 1) / tb, tb>>>(buf1, batch);
    mlp_kernel<<<GG, HH>>>(fW1, fb1, fW2, fb2, out);
}

// round 9
// speedup vs baseline: 1.9631x; 1.1454x over previous
#include <cuda_runtime.h>
#include <cuda_bf16.h>
#include <cstdint>

#define NN 50000
#define EE 500000
#define HH 128
#define GG 256

// ---------------- scratch (device globals; no allocs allowed) ----------------
static __device__ __align__(16) __nv_bfloat16 g_hb0[(size_t)NN * HH];  // gemm out (bf16)
static __device__ __align__(16) __nv_bfloat16 g_hb1[(size_t)NN * HH];  // agg1 out (bf16)
static __device__ __align__(16) float g_buf0[(size_t)NN * HH];         // agg2 out (fp32)
static __device__ float g_deg[NN];
static __device__ float g_dinv[NN];
static __device__ float g_sn[NN];      // self-loop coeff = 1/deg
static __device__ int   g_cnt[NN];
static __device__ int   g_off[NN];
static __device__ int   g_part[256];   // scan partials
static __device__ int   g_pos[EE];
static __device__ __align__(8) int2 g_edge[EE];   // CSR: {src, normalized w as bits}
static __device__ __align__(16) float g_pooled[GG * HH];
static __device__ float g_gcnt[GG];
// bf16 hi/lo weight images, plain row-major [128][128] (32KB each)
static __device__ __align__(16) unsigned char g_W1h[32768], g_W1l[32768];
static __device__ __align__(16) unsigned char g_W2h[32768], g_W2l[32768];

// ---------------- helpers ----------------
__device__ __forceinline__ float4 bf4(uint2 u) {
    __nv_bfloat162 a = *reinterpret_cast<__nv_bfloat162*>(&u.x);
    __nv_bfloat162 b = *reinterpret_cast<__nv_bfloat162*>(&u.y);
    float2 fa = __bfloat1622float2(a), fb = __bfloat1622float2(b);
    return make_float4(fa.x, fa.y, fb.x, fb.y);
}
__device__ __forceinline__ uint2 pk4(float4 v) {
    __nv_bfloat162 a = __float22bfloat162_rn(make_float2(v.x, v.y));
    __nv_bfloat162 b = __float22bfloat162_rn(make_float2(v.z, v.w));
    uint2 u;
    u.x = *reinterpret_cast<uint32_t*>(&a);
    u.y = *reinterpret_cast<uint32_t*>(&b);
    return u;
}

// ---------------- fused setup: init state + convert weights ------------------
__global__ void setup_kernel(const float* __restrict__ W1, const float* __restrict__ W2) {
    int blk = blockIdx.x, t = threadIdx.x;
    int i = blk * 256 + t;
    if (i < NN) { g_deg[i] = 1.0f; g_cnt[i] = 0; }
    if (i < GG * HH) g_pooled[i] = 0.0f;
    if (i < GG) g_gcnt[i] = 0.0f;
    if (blk >= 196) {
        const float* W = (blk == 197) ? W2 : W1;
        unsigned char* oh = (blk == 197) ? g_W2h : g_W1h;
        unsigned char* ol = (blk == 197) ? g_W2l : g_W1l;
        int r = t >> 1;
        int c0 = (t & 1) * 64;
        for (int c = c0; c < c0 + 64; c += 2) {
            float a0 = W[r * HH + c], a1 = W[r * HH + c + 1];
            __nv_bfloat16 h0 = __float2bfloat16(a0), h1 = __float2bfloat16(a1);
            __nv_bfloat16 l0 = __float2bfloat16(a0 - __bfloat162float(h0));
            __nv_bfloat16 l1 = __float2bfloat16(a1 - __bfloat162float(h1));
            uint32_t off = (uint32_t)(r * HH + c) * 2;
            *(uint32_t*)(oh + off) = ((uint32_t)__bfloat16_as_ushort(h1) << 16) | __bfloat16_as_ushort(h0);
            *(uint32_t*)(ol + off) = ((uint32_t)__bfloat16_as_ushort(l1) << 16) | __bfloat16_as_ushort(l0);
        }
    }
}

__global__ void count_kernel(const int* __restrict__ dst, const float* __restrict__ ew) {
    int e = blockIdx.x * blockDim.x + threadIdx.x;
    if (e >= EE) return;
    int d = dst[e];
    atomicAdd(&g_deg[d], ew[e]);
    g_pos[e] = atomicAdd(&g_cnt[d], 1);
}

// scanA: per-block local exclusive scan into g_off, block totals into g_part
__global__ void scanA_kernel() {        // 196 blocks x 256
    __shared__ int sh[256];
    int t = threadIdx.x;
    int i = blockIdx.x * 256 + t;
    int v = (i < NN) ? g_cnt[i] : 0;
    sh[t] = v;
    __syncthreads();
    #pragma unroll
    for (int s = 1; s < 256; s <<= 1) {
        int u = (t >= s) ? sh[t - s] : 0;
        __syncthreads();
        sh[t] += u;
        __syncthreads();
    }
    if (i < NN) g_off[i] = sh[t] - v;
    if (t == 255) g_part[blockIdx.x] = sh[255];
}
// scanB: every block re-scans the 196 partials locally, adds base, fuses dinv
__global__ void scanB_kernel() {        // 196 blocks x 256
    __shared__ int sp[256];
    int t = threadIdx.x;
    const int nb = (NN + 255) / 256;    // 196
    sp[t] = (t < nb) ? g_part[t] : 0;
    __syncthreads();
    #pragma unroll
    for (int s = 1; s < 256; s <<= 1) {
        int u = (t >= s) ? sp[t - s] : 0;
        __syncthreads();
        sp[t] += u;
        __syncthreads();
    }
    int base = blockIdx.x ? sp[blockIdx.x - 1] : 0;
    int i = blockIdx.x * 256 + t;
    if (i < NN) {
        g_off[i] += base;
        float d = rsqrtf(g_deg[i]);   // deg >= 1 always
        g_dinv[i] = d;
        g_sn[i] = d * d;
    }
}

__global__ void scatter_kernel(const int* __restrict__ src, const int* __restrict__ dst,
                               const float* __restrict__ ew) {
    int e = blockIdx.x * blockDim.x + threadIdx.x;
    if (e >= EE) return;
    int d = dst[e];
    int s = src[e];
    int idx = g_off[d] + g_pos[e];
    float w = g_dinv[s] * ew[e] * g_dinv[d];   // pre-normalized
    g_edge[idx] = make_int2(s, __float_as_int(w));
}

// ---------------- HMMA GEMM: C[NN x 128] = A[NN x 128] @ W^T, bf16 out --------
// AF32: A fp32 -> hi/lo split, 3 passes.  !AF32: A already bf16, 2 passes.
#define SROW 136
#define OA_H 0
#define OA_L (1 * 34816)
#define OW_H (2 * 34816)
#define OW_L (3 * 34816)
#define GSMEM_BYTES (4 * 34816)

__device__ __forceinline__ void mma_bf16(float* c, const uint32_t* a, const uint32_t* b) {
    asm volatile(
        "mma.sync.aligned.m16n8k16.row.col.f32.bf16.bf16.f32 "
        "{%0,%1,%2,%3}, {%4,%5,%6,%7}, {%8,%9}, {%0,%1,%2,%3};"
        : "+f"(c[0]), "+f"(c[1]), "+f"(c[2]), "+f"(c[3])
        : "r"(a[0]), "r"(a[1]), "r"(a[2]), "r"(a[3]), "r"(b[0]), "r"(b[1]));
}

template<bool AF32>
__global__ void __launch_bounds__(256) gemm_mma_kernel(
    const void* __restrict__ Ain,
    const unsigned char* __restrict__ Wh,
    const unsigned char* __restrict__ Wl,
    uint32_t* __restrict__ C           // bf16x2-packed output
) {
    extern __shared__ __align__(16) unsigned char smem[];
    int t = threadIdx.x;
    int rowBase = blockIdx.x * 128;

    if (AF32) {
        const float* A = (const float*)Ain;
        #pragma unroll
        for (int i = 0; i < 16; i++) {
            int idx = t + i * 256;
            int row = idx >> 5;
            int col = (idx & 31) << 2;
            float4 v = make_float4(0.f, 0.f, 0.f, 0.f);
            int gr = rowBase + row;
            if (gr < NN) v = *(const float4*)(A + (size_t)gr * HH + col);
            __nv_bfloat16 h0 = __float2bfloat16(v.x), h1 = __float2bfloat16(v.y);
            __nv_bfloat16 h2 = __float2bfloat16(v.z), h3 = __float2bfloat16(v.w);
            __nv_bfloat16 l0 = __float2bfloat16(v.x - __bfloat162float(h0));
            __nv_bfloat16 l1 = __float2bfloat16(v.y - __bfloat162float(h1));
            __nv_bfloat16 l2 = __float2bfloat16(v.z - __bfloat162float(h2));
            __nv_bfloat16 l3 = __float2bfloat16(v.w - __bfloat162float(h3));
            uint32_t off = (uint32_t)(row * SROW + col) * 2;
            uint2 ph, pl;
            ph.x = ((uint32_t)__bfloat16_as_ushort(h1) << 16) | __bfloat16_as_ushort(h0);
            ph.y = ((uint32_t)__bfloat16_as_ushort(h3) << 16) | __bfloat16_as_ushort(h2);
            pl.x = ((uint32_t)__bfloat16_as_ushort(l1) << 16) | __bfloat16_as_ushort(l0);
            pl.y = ((uint32_t)__bfloat16_as_ushort(l3) << 16) | __bfloat16_as_ushort(l2);
            *(uint2*)(smem + OA_H + off) = ph;
            *(uint2*)(smem + OA_L + off) = pl;
        }
    } else {
        const uint2* A = (const uint2*)Ain;   // bf16 rows: 32 uint2 per row
        #pragma unroll
        for (int i = 0; i < 16; i++) {
            int idx = t + i * 256;
            int row = idx >> 5;
            int col = (idx & 31) << 2;
            uint2 v = make_uint2(0u, 0u);
            int gr = rowBase + row;
            if (gr < NN) v = A[(size_t)gr * 32 + (idx & 31)];
            *(uint2*)(smem + OA_H + (uint32_t)(row * SROW + col) * 2) = v;
        }
    }
    {
        const uint2* gh = (const uint2*)Wh;
        const uint2* gl = (const uint2*)Wl;
        #pragma unroll
        for (int i = 0; i < 16; i++) {
            int idx = t + i * 256;
            int row = idx >> 5;
            int col = (idx & 31) << 2;
            uint32_t off = (uint32_t)(row * SROW + col) * 2;
            *(uint2*)(smem + OW_H + off) = gh[idx];
            *(uint2*)(smem + OW_L + off) = gl[idx];
        }
    }
    __syncthreads();

    int warp = t >> 5, lane = t & 31;
    int mrow = (warp >> 1) * 32;
    int ncol = (warp & 1) * 64;
    int qrow = lane >> 2, qp = lane & 3;

    float acc[2][8][4];
    #pragma unroll
    for (int mt = 0; mt < 2; mt++)
        #pragma unroll
        for (int nt = 0; nt < 8; nt++)
            #pragma unroll
            for (int q = 0; q < 4; q++) acc[mt][nt][q] = 0.f;

    #pragma unroll
    for (int k0 = 0; k0 < HH; k0 += 16) {
        int cb = k0 + qp * 2;
        uint32_t ah[2][4], al[2][4], wh[8][2], wl[8][2];
        #pragma unroll
        for (int mt = 0; mt < 2; mt++) {
            int r = mrow + mt * 16 + qrow;
            uint32_t o00 = (uint32_t)(r * SROW + cb) * 2;
            uint32_t o10 = o00 + 8u * SROW * 2;
            ah[mt][0] = *(const uint32_t*)(smem + OA_H + o00);
            ah[mt][1] = *(const uint32_t*)(smem + OA_H + o10);
            ah[mt][2] = *(const uint32_t*)(smem + OA_H + o00 + 16);
            ah[mt][3] = *(const uint32_t*)(smem + OA_H + o10 + 16);
            if (AF32) {
                al[mt][0] = *(const uint32_t*)(smem + OA_L + o00);
                al[mt][1] = *(const uint32_t*)(smem + OA_L + o10);
                al[mt][2] = *(const uint32_t*)(smem + OA_L + o00 + 16);
                al[mt][3] = *(const uint32_t*)(smem + OA_L + o10 + 16);
            }
        }
        #pragma unroll
        for (int nt = 0; nt < 8; nt++) {
            int n = ncol + nt * 8 + qrow;
            uint32_t o = (uint32_t)(n * SROW + cb) * 2;
            wh[nt][0] = *(const uint32_t*)(smem + OW_H + o);
            wh[nt][1] = *(const uint32_t*)(smem + OW_H + o + 16);
            wl[nt][0] = *(const uint32_t*)(smem + OW_L + o);
            wl[nt][1] = *(const uint32_t*)(smem + OW_L + o + 16);
        }
        #pragma unroll
        for (int mt = 0; mt < 2; mt++)
            #pragma unroll
            for (int nt = 0; nt < 8; nt++) {
                mma_bf16(acc[mt][nt], ah[mt], wh[nt]);
                mma_bf16(acc[mt][nt], ah[mt], wl[nt]);
                if (AF32) mma_bf16(acc[mt][nt], al[mt], wh[nt]);
            }
    }

    // store bf16-packed
    #pragma unroll
    for (int mt = 0; mt < 2; mt++) {
        int r0 = rowBase + mrow + mt * 16 + qrow;
        #pragma unroll
        for (int nt = 0; nt < 8; nt++) {
            int cc = ncol + nt * 8 + qp * 2;
            if (r0 < NN) {
                __nv_bfloat162 p = __float22bfloat162_rn(make_float2(acc[mt][nt][0], acc[mt][nt][1]));
                C[(size_t)r0 * 64 + (cc >> 1)] = *reinterpret_cast<uint32_t*>(&p);
            }
            if (r0 + 8 < NN) {
                __nv_bfloat162 p = __float22bfloat162_rn(make_float2(acc[mt][nt][2], acc[mt][nt][3]));
                C[(size_t)(r0 + 8) * 64 + (cc >> 1)] = *reinterpret_cast<uint32_t*>(&p);
            }
        }
    }
}

// ---------------- aggregation: out[n] = relu(h[n]/deg + sum h[s]*norm + b) ------
// bf16 gather (256 B/row), fp32 accumulate; OUTB -> bf16 out else fp32 out.
template<bool OUTB>
__global__ void agg_kernel(const __nv_bfloat16* __restrict__ h,
                           const float* __restrict__ bias, void* __restrict__ outp) {
    int w = (blockIdx.x * blockDim.x + threadIdx.x) >> 5;
    int lane = threadIdx.x & 31;
    if (w >= NN) return;
    int n = w;
    float sn = g_sn[n];
    const uint2* hb = (const uint2*)h;
    float4 hv = bf4(hb[(size_t)n * 32 + lane]);
    float4 acc = make_float4(hv.x * sn, hv.y * sn, hv.z * sn, hv.w * sn);
    int o = g_off[n], c = g_cnt[n];
    const int2* ep = g_edge + o;
    for (int j = 0; j < c; j++) {
        int2 e = ep[j];
        float nr = __int_as_float(e.y);
        float4 v = bf4(hb[(size_t)e.x * 32 + lane]);
        acc.x += v.x * nr; acc.y += v.y * nr; acc.z += v.z * nr; acc.w += v.w * nr;
    }
    float4 b = *reinterpret_cast<const float4*>(bias + (lane << 2));
    float4 r = make_float4(fmaxf(acc.x + b.x, 0.f), fmaxf(acc.y + b.y, 0.f),
                           fmaxf(acc.z + b.z, 0.f), fmaxf(acc.w + b.w, 0.f));
    if (OUTB) {
        ((uint2*)outp)[(size_t)n * 32 + lane] = pk4(r);
    } else {
        *reinterpret_cast<float4*>((float*)outp + (size_t)n * HH + (lane << 2)) = r;
    }
}

// ---------------- pooling (batch sorted; run-accumulate + atomic flush) ---------
#define CHUNK 32
__global__ void pool_kernel(const float* __restrict__ h, const int* __restrict__ batch) {
    int w = (blockIdx.x * blockDim.x + threadIdx.x) >> 5;
    int lane = threadIdx.x & 31;
    int start = w * CHUNK;
    if (start >= NN) return;
    int end = min(NN, start + CHUNK);
    int cur = batch[start];
    float4 acc = make_float4(0.f, 0.f, 0.f, 0.f);
    float cnt = 0.f;
    for (int i = start; i < end; i++) {
        int g = batch[i];
        if (g != cur) {
            float* p = &g_pooled[(size_t)cur * HH + (lane << 2)];
            atomicAdd(p + 0, acc.x); atomicAdd(p + 1, acc.y);
            atomicAdd(p + 2, acc.z); atomicAdd(p + 3, acc.w);
            if (lane == 0) atomicAdd(&g_gcnt[cur], cnt);
            acc = make_float4(0.f, 0.f, 0.f, 0.f); cnt = 0.f; cur = g;
        }
        float4 v = *reinterpret_cast<const float4*>(h + (size_t)i * HH + (lane << 2));
        acc.x += v.x; acc.y += v.y; acc.z += v.z; acc.w += v.w;
        cnt += 1.f;
    }
    float* p = &g_pooled[(size_t)cur * HH + (lane << 2)];
    atomicAdd(p + 0, acc.x); atomicAdd(p + 1, acc.y);
    atomicAdd(p + 2, acc.z); atomicAdd(p + 3, acc.w);
    if (lane == 0) atomicAdd(&g_gcnt[cur], cnt);
}

// ---------------- head MLP ----------------
__global__ void mlp_kernel(const float* __restrict__ fW1, const float* __restrict__ fb1,
                           const float* __restrict__ fW2, const float* __restrict__ fb2,
                           float* __restrict__ out) {
    __shared__ float p[HH];
    __shared__ float red[4];
    int g = blockIdx.x, j = threadIdx.x;
    float c = fmaxf(g_gcnt[g], 1.0f);
    p[j] = g_pooled[(size_t)g * HH + j] / c;
    __syncthreads();
    float acc = fb1[j];
    #pragma unroll 8
    for (int k = 0; k < HH; k++) acc += p[k] * fW1[(size_t)j * HH + k];
    float o = fmaxf(acc, 0.f) * fW2[j];
    #pragma unroll
    for (int s = 16; s > 0; s >>= 1) o += __shfl_down_sync(0xffffffffu, o, s);
    if ((j & 31) == 0) red[j >> 5] = o;
    __syncthreads();
    if (j == 0) out[g] = red[0] + red[1] + red[2] + red[3] + fb2[0];
}

// ---------------- launch ----------------
extern "C" void kernel_launch(void* const* d_in, const int* in_sizes, int n_in,
                              void* d_out, int out_size) {
    const float* x     = (const float*)d_in[0];
    const int*   ei    = (const int*)d_in[1];
    const float* ea    = (const float*)d_in[2];
    const int*   batch = (const int*)d_in[3];
    const float* W1    = (const float*)d_in[4];
    const float* b1    = (const float*)d_in[5];
    const float* W2    = (const float*)d_in[6];
    const float* b2    = (const float*)d_in[7];
    const float* fW1   = (const float*)d_in[8];
    const float* fb1   = (const float*)d_in[9];
    const float* fW2   = (const float*)d_in[10];
    const float* fb2   = (const float*)d_in[11];
    float* out = (float*)d_out;

    const int* src = ei;
    const int* dst = ei + EE;

    void *ph0, *ph1, *pf0, *pw1h, *pw1l, *pw2h, *pw2l;
    cudaGetSymbolAddress(&ph0, g_hb0);
    cudaGetSymbolAddress(&ph1, g_hb1);
    cudaGetSymbolAddress(&pf0, g_buf0);
    cudaGetSymbolAddress(&pw1h, g_W1h);
    cudaGetSymbolAddress(&pw1l, g_W1l);
    cudaGetSymbolAddress(&pw2h, g_W2h);
    cudaGetSymbolAddress(&pw2l, g_W2l);
    __nv_bfloat16* hb0 = (__nv_bfloat16*)ph0;
    __nv_bfloat16* hb1 = (__nv_bfloat16*)ph1;
    float* fbuf = (float*)pf0;

    cudaFuncSetAttribute(gemm_mma_kernel<true>, cudaFuncAttributeMaxDynamicSharedMemorySize, GSMEM_BYTES);
    cudaFuncSetAttribute(gemm_mma_kernel<false>, cudaFuncAttributeMaxDynamicSharedMemorySize, GSMEM_BYTES);

    const int tb = 256;
    const int nblk = (NN + tb - 1) / tb;    // 196
    const int eblk = (EE + tb - 1) / tb;    // 1954
    const int ggrid = (NN + 127) / 128;     // 391

    cudaStream_t s2 = 0;
    cudaEvent_t evA = 0, evB = 0;
    bool par = (cudaStreamCreateWithFlags(&s2, cudaStreamNonBlocking) == cudaSuccess);
    if (par) par = (cudaEventCreateWithFlags(&evA, cudaEventDisableTiming) == cudaSuccess);
    if (par) par = (cudaEventCreateWithFlags(&evB, cudaEventDisableTiming) == cudaSuccess);
    cudaStream_t sc = par ? s2 : (cudaStream_t)0;

    setup_kernel<<<198, 256>>>(W1, W2);
    if (par) {
        cudaEventRecord(evA, 0);
        cudaStreamWaitEvent(s2, evA, 0);
    }
    // CSR branch (side stream)
    count_kernel<<<eblk, tb, 0, sc>>>(dst, ea);
    scanA_kernel<<<nblk, tb, 0, sc>>>();
    scanB_kernel<<<nblk, tb, 0, sc>>>();
    scatter_kernel<<<eblk, tb, 0, sc>>>(src, dst, ea);
    // GEMM1 branch (main stream)
    gemm_mma_kernel<true><<<ggrid, 256, GSMEM_BYTES>>>(x, (const unsigned char*)pw1h,
                                                       (const unsigned char*)pw1l, (uint32_t*)hb0);
    if (par) {
        cudaEventRecord(evB, s2);
        cudaStreamWaitEvent(0, evB, 0);
    }

    agg_kernel<true><<<((NN * 32) + tb - 1) / tb, tb>>>(hb0, b1, hb1);
    gemm_mma_kernel<false><<<ggrid, 256, GSMEM_BYTES>>>(hb1, (const unsigned char*)pw2h,
                                                        (const unsigned char*)pw2l, (uint32_t*)hb0);
    agg_kernel<false><<<((NN * 32) + tb - 1) / tb, tb>>>(hb0, b2, fbuf);

    int pwarps = (NN + CHUNK - 1) / CHUNK;
    pool_kernel<<<((pwarps * 32) + tb - 1) / tb, tb>>>(fbuf, batch);
    mlp_kernel<<<GG, HH>>>(fW1, fb1, fW2, fb2, out);
}